// round 2
// baseline (speedup 1.0000x reference)
#include <cuda_runtime.h>

#define G     4096
#define NB    2          // batch
#define NH    32         // hidden / out channels
#define NG    128        // interpolation intervals
#define NP    (NG + 3)   // table points (1 guard each side)

// ---------------- scratch (device globals; no allocation) ----------------
__device__ float    g_h1 [NB * G * NH];   // elu(infer) output
__device__ float    g_mid[NB * G * NH];   // block1 output
__device__ float    g_bnv[NB * G * NH];   // batchnorm output
__device__ float    g_ssrc[NB * G];       // s_src per node
__device__ float    g_u   [NB * G];       // s_dst + b_e per node
__device__ unsigned g_minmax[NB * 2];     // per batch: [minkey, maxkey]
__device__ float    g_tab[NB * NP * 33];  // S table: 32 h-channels + count

// ---------------- helpers ----------------
__device__ __forceinline__ float sigm(float x) {
    return __fdividef(1.0f, 1.0f + __expf(-x));
}
__device__ __forceinline__ float eluf(float x) {
    return x > 0.0f ? x : (__expf(x) - 1.0f);
}
__device__ __forceinline__ unsigned fkey(float f) {
    unsigned u = __float_as_uint(f);
    return (u & 0x80000000u) ? ~u : (u | 0x80000000u);
}
__device__ __forceinline__ float funkey(unsigned k) {
    return (k & 0x80000000u) ? __uint_as_float(k ^ 0x80000000u)
                             : __uint_as_float(~k);
}

// ---------------- k_infer: h = elu(x @ W_infer + b_infer) ----------------
__global__ void k_infer(const float* __restrict__ x,
                        const float* __restrict__ W,
                        const float* __restrict__ b) {
    int idx = blockIdx.x * blockDim.x + threadIdx.x;   // < NB*G*32
    int c  = idx & 31;
    int bg = idx >> 5;
    const float* xr = x + bg * 8;
    float v = b[c];
#pragma unroll
    for (int k = 0; k < 8; k++) v += xr[k] * W[k * 32 + c];
    g_h1[idx] = eluf(v);
}

// ---------------- k_reset: init minmax keys ----------------
__global__ void k_reset() {
    int t = threadIdx.x;
    if (t < NB) { g_minmax[t * 2] = 0xFFFFFFFFu; g_minmax[t * 2 + 1] = 0u; }
}

// ------------- k_edge: s_src, u = s_dst + b_e, and u-range -------------
__global__ void k_edge(const float* __restrict__ hin,
                       const float* __restrict__ We,
                       const float* __restrict__ be) {
    int w    = (blockIdx.x * blockDim.x + threadIdx.x) >> 5;  // node index bg
    int lane = threadIdx.x & 31;
    if (w >= NB * G) return;
    float h  = hin[w * 32 + lane];
    float p1 = h * We[lane];        // x_j part  (rows 0..31)
    float p2 = h * We[32 + lane];   // x_i part  (rows 32..63)
#pragma unroll
    for (int o = 16; o > 0; o >>= 1) {
        p1 += __shfl_down_sync(~0u, p1, o);
        p2 += __shfl_down_sync(~0u, p2, o);
    }
    if (lane == 0) {
        g_ssrc[w] = p1;
        float u = p2 + be[0];
        g_u[w] = u;
        int b = w / G;
        unsigned k = fkey(u);
        atomicMin(&g_minmax[b * 2], k);
        atomicMax(&g_minmax[b * 2 + 1], k);
    }
}

// ------------- k_table: S[b][p][c] = sum_j sigmoid(u_p + v_j) * [h_j;1] -------------
__global__ void __launch_bounds__(256) k_table(const float* __restrict__ hin) {
    int bp = blockIdx.x;
    int b  = bp / NP;
    int p  = bp % NP;
    float umin  = funkey(g_minmax[b * 2]);
    float umax  = funkey(g_minmax[b * 2 + 1]);
    float delta = fmaxf(umax - umin, 1e-30f) / NG;
    float up    = umin + (p - 1) * delta;

    __shared__ float se[256];
    __shared__ float spart[8][32];
    __shared__ float ssum[8];
    int t = threadIdx.x, w = t >> 5, lane = t & 31;

    float acc = 0.0f, es = 0.0f;
    const float* hb = hin + (size_t)b * G * 32;
    const float* vb = g_ssrc + b * G;

    for (int tile = 0; tile < G / 256; tile++) {
        int j = tile * 256 + t;
        float e = sigm(up + vb[j]);
        se[t] = e;
        es += e;
        __syncthreads();
        const float* hbase = hb + (size_t)(tile * 256 + w * 32) * 32;
#pragma unroll 8
        for (int q = 0; q < 32; q++) acc += se[w * 32 + q] * hbase[q * 32 + lane];
        __syncthreads();
    }
    spart[w][lane] = acc;
#pragma unroll
    for (int o = 16; o > 0; o >>= 1) es += __shfl_down_sync(~0u, es, o);
    if (lane == 0) ssum[w] = es;
    __syncthreads();
    if (w == 0) {
        float s = spart[0][lane];
#pragma unroll
        for (int q = 1; q < 8; q++) s += spart[q][lane];
        g_tab[bp * 33 + lane] = s;
        if (lane == 0) {
            float z = 0.0f;
#pragma unroll
            for (int q = 0; q < 8; q++) z += ssum[q];
            g_tab[bp * 33 + 32] = z;
        }
    }
}

// ------------- k_rows: per-row sparse scan + dense interp + node MLPs -------------
__global__ void __launch_bounds__(256) k_rows(
        const float* __restrict__ hin, const float* __restrict__ adj,
        const float* __restrict__ Wn,  const float* __restrict__ bnv,
        const float* __restrict__ Wm,  const float* __restrict__ bmv,
        float coef, float* __restrict__ out) {
    int i = blockIdx.x;
    int t = threadIdx.x, w = t >> 5, lane = t & 31;

    __shared__ unsigned short slist[1024];
    __shared__ float se0[1024];
    __shared__ float se1[1024];
    __shared__ int   scnt;
    __shared__ float spart[8][2][32];
    __shared__ float srs[2];
    __shared__ float srowtot[2];
    __shared__ float srecv[2][64];
    __shared__ float srec2[2][32];

    float u0 = g_u[i], u1 = g_u[G + i];
    float sc = 1.0f - coef;
    float acc0 = 0.0f, acc1 = 0.0f;
    if (t == 0) { srs[0] = 0.0f; srs[1] = 0.0f; }

    const float4* arow = (const float4*)(adj + (size_t)i * G);

    for (int seg = 0; seg < 4; seg++) {
        __syncthreads();
        if (t == 0) scnt = 0;
        __syncthreads();
        float4 a = arow[seg * 256 + t];
        int jb = seg * 1024 + t * 4;
        if (a.x != 0.0f) { int p = atomicAdd(&scnt, 1); slist[p] = (unsigned short)(jb); }
        if (a.y != 0.0f) { int p = atomicAdd(&scnt, 1); slist[p] = (unsigned short)(jb + 1); }
        if (a.z != 0.0f) { int p = atomicAdd(&scnt, 1); slist[p] = (unsigned short)(jb + 2); }
        if (a.w != 0.0f) { int p = atomicAdd(&scnt, 1); slist[p] = (unsigned short)(jb + 3); }
        __syncthreads();
        int cnt = scnt;
        // e phase: compute (1-coef)*sigmoid for listed edges, both batches
        for (int base = 0; base < cnt; base += 256) {
            int idx = base + t;
            float e0 = 0.0f, e1 = 0.0f;
            if (idx < cnt) {
                int j = slist[idx];
                e0 = sc * sigm(u0 + g_ssrc[j]);
                e1 = sc * sigm(u1 + g_ssrc[G + j]);
                se0[idx] = e0;
                se1[idx] = e1;
            }
            float r0 = e0, r1 = e1;
#pragma unroll
            for (int o = 16; o > 0; o >>= 1) {
                r0 += __shfl_down_sync(~0u, r0, o);
                r1 += __shfl_down_sync(~0u, r1, o);
            }
            if (lane == 0) { atomicAdd(&srs[0], r0); atomicAdd(&srs[1], r1); }
        }
        __syncthreads();
        // accumulate e * h[j]  (warp = edge slice, lane = channel)
        for (int idx = w; idx < cnt; idx += 8) {
            int j = slist[idx];
            acc0 += se0[idx] * hin[(size_t)j * 32 + lane];
            acc1 += se1[idx] * hin[(size_t)(G + j) * 32 + lane];
        }
    }
    spart[w][0][lane] = acc0;
    spart[w][1][lane] = acc1;
    __syncthreads();

    // dense (table interpolation) + combine: threads t<66 -> (b, c in 0..32)
    if (t < 66) {
        int b = t / 33, c = t % 33;
        float umn = funkey(g_minmax[b * 2]);
        float umx = funkey(g_minmax[b * 2 + 1]);
        float delta = fmaxf(umx - umn, 1e-30f) / NG;
        float u = (b == 0) ? u0 : u1;
        float s = (u - umn) / delta;
        s = fminf(fmaxf(s, 0.0f), (float)NG);
        int k = (int)s;
        if (k > NG - 1) k = NG - 1;
        float f = s - (float)k;
        float w0 = f * (-0.5f + f * (1.0f - 0.5f * f));
        float w1 = 1.0f + f * f * (-2.5f + 1.5f * f);
        float w2 = f * (0.5f + f * (2.0f - 1.5f * f));
        float w3 = f * f * (-0.5f + 0.5f * f);
        const float* tb = g_tab + (size_t)(b * NP + k) * 33 + c;
        float dense = w0 * tb[0] + w1 * tb[33] + w2 * tb[66] + w3 * tb[99];
        if (c < 32) {
            float sp = 0.0f;
#pragma unroll
            for (int q = 0; q < 8; q++) sp += spart[q][b][c];
            srecv[b][c] = sp + coef * dense;          // recv_src
        } else {
            srowtot[b] = srs[b] + coef * dense;       // row sum of e
        }
    }
    __syncthreads();
    if (t < 64) {                                     // recv_dst = h_i * rowsum
        int b = t >> 5, c = t & 31;
        srecv[b][32 + c] = hin[(size_t)(b * G + i) * 32 + c] * srowtot[b];
    }
    __syncthreads();
    if (t < 64) {                                     // nodes MLP + elu
        int b = t >> 5, o = t & 31;
        float v = bnv[o];
#pragma unroll
        for (int k2 = 0; k2 < 64; k2++) v += srecv[b][k2] * Wn[k2 * 32 + o];
        srec2[b][o] = eluf(v);
    }
    __syncthreads();
    if (t < 64) {                                     // merge MLP + elu
        int b = t >> 5, o = t & 31;
        float v = bmv[o];
#pragma unroll
        for (int k2 = 0; k2 < 32; k2++) v += srec2[b][k2] * Wm[k2 * 32 + o];
#pragma unroll
        for (int k2 = 0; k2 < 32; k2++)
            v += hin[(size_t)(b * G + i) * 32 + k2] * Wm[(32 + k2) * 32 + o];
        out[(size_t)(b * G + i) * 32 + o] = eluf(v);
    }
}

// ------------- k_bn: BatchNorm1d over (batch, feature) per gene -------------
__global__ void k_bn(const float* __restrict__ gamma,
                     const float* __restrict__ beta) {
    int gidx = (blockIdx.x * blockDim.x + threadIdx.x) >> 5;
    int lane = threadIdx.x & 31;
    if (gidx >= G) return;
    float v0 = g_mid[(size_t)gidx * 32 + lane];
    float v1 = g_mid[(size_t)(G + gidx) * 32 + lane];
    float s = v0 + v1, ss = v0 * v0 + v1 * v1;
#pragma unroll
    for (int o = 16; o > 0; o >>= 1) {
        s  += __shfl_xor_sync(~0u, s, o);
        ss += __shfl_xor_sync(~0u, ss, o);
    }
    float mean = s * (1.0f / 64.0f);
    float var  = ss * (1.0f / 64.0f) - mean * mean;
    float rstd = rsqrtf(var + 1e-5f);
    float ga = gamma[gidx], be = beta[gidx];
    g_bnv[(size_t)gidx * 32 + lane]       = (v0 - mean) * rstd * ga + be;
    g_bnv[(size_t)(G + gidx) * 32 + lane] = (v1 - mean) * rstd * ga + be;
}

// ---------------- launch ----------------
extern "C" void kernel_launch(void* const* d_in, const int* in_sizes, int n_in,
                              void* d_out, int out_size) {
    const float* x   = (const float*)d_in[0];
    const float* e1  = (const float*)d_in[1];
    const float* e2  = (const float*)d_in[2];
    const float* Wi  = (const float*)d_in[3];
    const float* bi  = (const float*)d_in[4];
    const float* We1 = (const float*)d_in[5];
    const float* be1 = (const float*)d_in[6];
    const float* We2 = (const float*)d_in[7];
    const float* be2 = (const float*)d_in[8];
    const float* Wn1 = (const float*)d_in[9];
    const float* bn1 = (const float*)d_in[10];
    const float* Wn2 = (const float*)d_in[11];
    const float* bn2 = (const float*)d_in[12];
    const float* Wm1 = (const float*)d_in[13];
    const float* bm1 = (const float*)d_in[14];
    const float* Wm2 = (const float*)d_in[15];
    const float* bm2 = (const float*)d_in[16];
    const float* gam = (const float*)d_in[17];
    const float* bet = (const float*)d_in[18];
    float* out = (float*)d_out;

    float *ph1, *pmid, *pbn;
    cudaGetSymbolAddress((void**)&ph1,  g_h1);
    cudaGetSymbolAddress((void**)&pmid, g_mid);
    cudaGetSymbolAddress((void**)&pbn,  g_bnv);

    const float ALPHA = 0.005f, BETA = 5e-5f;

    k_infer<<<(NB * G * 32) / 256, 256>>>(x, Wi, bi);

    // ---- block 1 ----
    k_reset<<<1, 32>>>();
    k_edge<<<(NB * G * 32) / 256, 256>>>(ph1, We1, be1);
    k_table<<<NB * NP, 256>>>(ph1);
    k_rows<<<G, 256>>>(ph1, e1, Wn1, bn1, Wm1, bm1, ALPHA, pmid);

    // ---- batchnorm ----
    k_bn<<<(G * 32) / 256, 256>>>(gam, bet);

    // ---- block 2 ----
    k_reset<<<1, 32>>>();
    k_edge<<<(NB * G * 32) / 256, 256>>>(pbn, We2, be2);
    k_table<<<NB * NP, 256>>>(pbn);
    k_rows<<<G, 256>>>(pbn, e2, Wn2, bn2, Wm2, bm2, BETA, out);

    (void)in_sizes; (void)n_in; (void)out_size;
}

// round 3
// speedup vs baseline: 1.3892x; 1.3892x over previous
#include <cuda_runtime.h>

#define G     4096
#define NB    2          // batch
#define NH    32         // hidden / out channels
#define NG    128        // interpolation intervals
#define NP    (NG + 3)   // table points (1 guard each side)
#define NCH   64         // j-chunk size for k_table

// ---------------- scratch (device globals; no allocation) ----------------
__device__ float    g_h1 [NB * G * NH];   // elu(infer) output
__device__ float    g_mid[NB * G * NH];   // block1 output
__device__ float    g_bnv[NB * G * NH];   // batchnorm output
__device__ float    g_ssrc[NB * G];       // s_src per node
__device__ float    g_u   [NB * G];       // s_dst + b_e per node
__device__ unsigned g_minmax[NB * 2];     // per batch: [minkey, maxkey]
__device__ float    g_tab[NB * NP * 33];  // S table: 32 h-channels + count

// ---------------- helpers ----------------
__device__ __forceinline__ float sigm(float x) {
    return __fdividef(1.0f, 1.0f + __expf(-x));
}
__device__ __forceinline__ float eluf(float x) {
    return x > 0.0f ? x : (__expf(x) - 1.0f);
}
__device__ __forceinline__ unsigned fkey(float f) {
    unsigned u = __float_as_uint(f);
    return (u & 0x80000000u) ? ~u : (u | 0x80000000u);
}
__device__ __forceinline__ float funkey(unsigned k) {
    return (k & 0x80000000u) ? __uint_as_float(k ^ 0x80000000u)
                             : __uint_as_float(~k);
}

// ---------------- k_infer: h = elu(x @ W_infer + b_infer) ----------------
__global__ void k_infer(const float* __restrict__ x,
                        const float* __restrict__ W,
                        const float* __restrict__ b) {
    int idx = blockIdx.x * blockDim.x + threadIdx.x;   // < NB*G*32
    int c  = idx & 31;
    int bg = idx >> 5;
    const float* xr = x + bg * 8;
    float v = b[c];
#pragma unroll
    for (int k = 0; k < 8; k++) v += xr[k] * W[k * 32 + c];
    g_h1[idx] = eluf(v);
}

// ---------------- k_reset: zero table + init minmax keys ----------------
__global__ void k_reset() {
    int idx = blockIdx.x * blockDim.x + threadIdx.x;
    if (idx < NB * NP * 33) g_tab[idx] = 0.0f;
    if (idx < NB) { g_minmax[idx * 2] = 0xFFFFFFFFu; g_minmax[idx * 2 + 1] = 0u; }
}

// ------------- k_edge: s_src, u = s_dst + b_e, and u-range -------------
__global__ void k_edge(const float* __restrict__ hin,
                       const float* __restrict__ We,
                       const float* __restrict__ be) {
    int w    = (blockIdx.x * blockDim.x + threadIdx.x) >> 5;  // node index bg
    int lane = threadIdx.x & 31;
    if (w >= NB * G) return;
    float h  = hin[w * 32 + lane];
    float p1 = h * We[lane];        // x_j part  (rows 0..31)
    float p2 = h * We[32 + lane];   // x_i part  (rows 32..63)
#pragma unroll
    for (int o = 16; o > 0; o >>= 1) {
        p1 += __shfl_down_sync(~0u, p1, o);
        p2 += __shfl_down_sync(~0u, p2, o);
    }
    if (lane == 0) {
        g_ssrc[w] = p1;
        float u = p2 + be[0];
        g_u[w] = u;
        int b = w / G;
        unsigned k = fkey(u);
        atomicMin(&g_minmax[b * 2], k);
        atomicMax(&g_minmax[b * 2 + 1], k);
    }
}

// ------------- k_table (tiled): partial S over a 64-node chunk -------------
// S[b][p][c] = sum_j sigmoid(u_p + v_j) * [h_j ; 1]
__global__ void __launch_bounds__(256) k_table(const float* __restrict__ hin) {
    int blk   = blockIdx.x;             // NB * (G/NCH)
    int b     = blk / (G / NCH);
    int chunk = blk % (G / NCH);
    int j0    = chunk * NCH;

    __shared__ float sh[NCH * 32];      // h chunk   (8 KB)
    __shared__ float sv[NCH];           // v chunk
    __shared__ float se[NP * NCH];      // e tile    (33.5 KB)

    int t = threadIdx.x, w = t >> 5, lane = t & 31;

    float umin  = funkey(g_minmax[b * 2]);
    float umax  = funkey(g_minmax[b * 2 + 1]);
    float delta = fmaxf(umax - umin, 1e-30f) / NG;

    // stage h chunk + v chunk
#pragma unroll
    for (int idx = t; idx < NCH * 32; idx += 256)
        sh[idx] = hin[(size_t)(b * G + j0) * 32 + idx];
    if (t < NCH) sv[t] = g_ssrc[b * G + j0 + t];
    __syncthreads();

    // e tile: 131 x 64 sigmoids, cooperative (no lane redundancy)
    for (int idx = t; idx < NP * NCH; idx += 256) {
        int p = idx >> 6;               // NCH = 64
        int j = idx & 63;
        float up = umin + (float)(p - 1) * delta;
        se[idx] = sigm(up + sv[j]);
    }
    __syncthreads();

    // accumulate: warp w owns p = w, w+8, ... ; lane = channel
    for (int p = w; p < NP; p += 8) {
        const float4* ep4 = (const float4*)(se + p * NCH);
        float acc = 0.0f;
#pragma unroll
        for (int j4 = 0; j4 < NCH / 4; j4++) {
            float4 e = ep4[j4];
            int j = j4 * 4;
            acc += e.x * sh[(j    ) * 32 + lane];
            acc += e.y * sh[(j + 1) * 32 + lane];
            acc += e.z * sh[(j + 2) * 32 + lane];
            acc += e.w * sh[(j + 3) * 32 + lane];
        }
        atomicAdd(&g_tab[(b * NP + p) * 33 + lane], acc);
        // count column: sum_j e
        const float* ep = se + p * NCH;
        float cs = ep[lane] + ep[32 + lane];
#pragma unroll
        for (int o = 16; o > 0; o >>= 1) cs += __shfl_down_sync(~0u, cs, o);
        if (lane == 0) atomicAdd(&g_tab[(b * NP + p) * 33 + 32], cs);
    }
}

// ------------- k_rows: per-row sparse scan + dense interp + node MLPs -------------
__global__ void __launch_bounds__(256) k_rows(
        const float* __restrict__ hin, const float* __restrict__ adj,
        const float* __restrict__ Wn,  const float* __restrict__ bnv,
        const float* __restrict__ Wm,  const float* __restrict__ bmv,
        float coef, float* __restrict__ out) {
    int i = blockIdx.x;
    int t = threadIdx.x, w = t >> 5, lane = t & 31;

    __shared__ unsigned short slist[1024];
    __shared__ float se0[1024];
    __shared__ float se1[1024];
    __shared__ int   scnt;
    __shared__ float spart[8][2][32];
    __shared__ float srs[2];
    __shared__ float srowtot[2];
    __shared__ float srecv[2][64];
    __shared__ float srec2[2][32];

    float u0 = g_u[i], u1 = g_u[G + i];
    float sc = 1.0f - coef;
    float acc0 = 0.0f, acc1 = 0.0f;
    if (t == 0) { srs[0] = 0.0f; srs[1] = 0.0f; }

    const float4* arow = (const float4*)(adj + (size_t)i * G);

    for (int seg = 0; seg < 4; seg++) {
        __syncthreads();
        if (t == 0) scnt = 0;
        __syncthreads();
        float4 a = arow[seg * 256 + t];
        int jb = seg * 1024 + t * 4;
        if (a.x != 0.0f) { int p = atomicAdd(&scnt, 1); slist[p] = (unsigned short)(jb); }
        if (a.y != 0.0f) { int p = atomicAdd(&scnt, 1); slist[p] = (unsigned short)(jb + 1); }
        if (a.z != 0.0f) { int p = atomicAdd(&scnt, 1); slist[p] = (unsigned short)(jb + 2); }
        if (a.w != 0.0f) { int p = atomicAdd(&scnt, 1); slist[p] = (unsigned short)(jb + 3); }
        __syncthreads();
        int cnt = scnt;
        // e phase: compute (1-coef)*sigmoid for listed edges, both batches
        for (int base = 0; base < cnt; base += 256) {
            int idx = base + t;
            float e0 = 0.0f, e1 = 0.0f;
            if (idx < cnt) {
                int j = slist[idx];
                e0 = sc * sigm(u0 + g_ssrc[j]);
                e1 = sc * sigm(u1 + g_ssrc[G + j]);
                se0[idx] = e0;
                se1[idx] = e1;
            }
            float r0 = e0, r1 = e1;
#pragma unroll
            for (int o = 16; o > 0; o >>= 1) {
                r0 += __shfl_down_sync(~0u, r0, o);
                r1 += __shfl_down_sync(~0u, r1, o);
            }
            if (lane == 0) { atomicAdd(&srs[0], r0); atomicAdd(&srs[1], r1); }
        }
        __syncthreads();
        // accumulate e * h[j]  (warp = edge slice, lane = channel)
        for (int idx = w; idx < cnt; idx += 8) {
            int j = slist[idx];
            acc0 += se0[idx] * hin[(size_t)j * 32 + lane];
            acc1 += se1[idx] * hin[(size_t)(G + j) * 32 + lane];
        }
    }
    spart[w][0][lane] = acc0;
    spart[w][1][lane] = acc1;
    __syncthreads();

    // dense (table interpolation) + combine: threads t<66 -> (b, c in 0..32)
    if (t < 66) {
        int b = t / 33, c = t % 33;
        float umn = funkey(g_minmax[b * 2]);
        float umx = funkey(g_minmax[b * 2 + 1]);
        float delta = fmaxf(umx - umn, 1e-30f) / NG;
        float u = (b == 0) ? u0 : u1;
        float s = (u - umn) / delta;
        s = fminf(fmaxf(s, 0.0f), (float)NG);
        int k = (int)s;
        if (k > NG - 1) k = NG - 1;
        float f = s - (float)k;
        float w0 = f * (-0.5f + f * (1.0f - 0.5f * f));
        float w1 = 1.0f + f * f * (-2.5f + 1.5f * f);
        float w2 = f * (0.5f + f * (2.0f - 1.5f * f));
        float w3 = f * f * (-0.5f + 0.5f * f);
        const float* tb = g_tab + (size_t)(b * NP + k) * 33 + c;
        float dense = w0 * tb[0] + w1 * tb[33] + w2 * tb[66] + w3 * tb[99];
        if (c < 32) {
            float sp = 0.0f;
#pragma unroll
            for (int q = 0; q < 8; q++) sp += spart[q][b][c];
            srecv[b][c] = sp + coef * dense;          // recv_src
        } else {
            srowtot[b] = srs[b] + coef * dense;       // row sum of e
        }
    }
    __syncthreads();
    if (t < 64) {                                     // recv_dst = h_i * rowsum
        int b = t >> 5, c = t & 31;
        srecv[b][32 + c] = hin[(size_t)(b * G + i) * 32 + c] * srowtot[b];
    }
    __syncthreads();
    if (t < 64) {                                     // nodes MLP + elu
        int b = t >> 5, o = t & 31;
        float v = bnv[o];
#pragma unroll
        for (int k2 = 0; k2 < 64; k2++) v += srecv[b][k2] * Wn[k2 * 32 + o];
        srec2[b][o] = eluf(v);
    }
    __syncthreads();
    if (t < 64) {                                     // merge MLP + elu
        int b = t >> 5, o = t & 31;
        float v = bmv[o];
#pragma unroll
        for (int k2 = 0; k2 < 32; k2++) v += srec2[b][k2] * Wm[k2 * 32 + o];
#pragma unroll
        for (int k2 = 0; k2 < 32; k2++)
            v += hin[(size_t)(b * G + i) * 32 + k2] * Wm[(32 + k2) * 32 + o];
        out[(size_t)(b * G + i) * 32 + o] = eluf(v);
    }
}

// ------------- k_bn: BatchNorm1d over (batch, feature) per gene -------------
__global__ void k_bn(const float* __restrict__ gamma,
                     const float* __restrict__ beta) {
    int gidx = (blockIdx.x * blockDim.x + threadIdx.x) >> 5;
    int lane = threadIdx.x & 31;
    if (gidx >= G) return;
    float v0 = g_mid[(size_t)gidx * 32 + lane];
    float v1 = g_mid[(size_t)(G + gidx) * 32 + lane];
    float s = v0 + v1, ss = v0 * v0 + v1 * v1;
#pragma unroll
    for (int o = 16; o > 0; o >>= 1) {
        s  += __shfl_xor_sync(~0u, s, o);
        ss += __shfl_xor_sync(~0u, ss, o);
    }
    float mean = s * (1.0f / 64.0f);
    float var  = ss * (1.0f / 64.0f) - mean * mean;
    float rstd = rsqrtf(var + 1e-5f);
    float ga = gamma[gidx], be = beta[gidx];
    g_bnv[(size_t)gidx * 32 + lane]       = (v0 - mean) * rstd * ga + be;
    g_bnv[(size_t)(G + gidx) * 32 + lane] = (v1 - mean) * rstd * ga + be;
}

// ---------------- launch ----------------
extern "C" void kernel_launch(void* const* d_in, const int* in_sizes, int n_in,
                              void* d_out, int out_size) {
    const float* x   = (const float*)d_in[0];
    const float* e1  = (const float*)d_in[1];
    const float* e2  = (const float*)d_in[2];
    const float* Wi  = (const float*)d_in[3];
    const float* bi  = (const float*)d_in[4];
    const float* We1 = (const float*)d_in[5];
    const float* be1 = (const float*)d_in[6];
    const float* We2 = (const float*)d_in[7];
    const float* be2 = (const float*)d_in[8];
    const float* Wn1 = (const float*)d_in[9];
    const float* bn1 = (const float*)d_in[10];
    const float* Wn2 = (const float*)d_in[11];
    const float* bn2 = (const float*)d_in[12];
    const float* Wm1 = (const float*)d_in[13];
    const float* bm1 = (const float*)d_in[14];
    const float* Wm2 = (const float*)d_in[15];
    const float* bm2 = (const float*)d_in[16];
    const float* gam = (const float*)d_in[17];
    const float* bet = (const float*)d_in[18];
    float* out = (float*)d_out;

    float *ph1, *pmid, *pbn;
    cudaGetSymbolAddress((void**)&ph1,  g_h1);
    cudaGetSymbolAddress((void**)&pmid, g_mid);
    cudaGetSymbolAddress((void**)&pbn,  g_bnv);

    const float ALPHA = 0.005f, BETA = 5e-5f;
    const int RESET_GRID = (NB * NP * 33 + 255) / 256;

    k_infer<<<(NB * G * 32) / 256, 256>>>(x, Wi, bi);

    // ---- block 1 ----
    k_reset<<<RESET_GRID, 256>>>();
    k_edge<<<(NB * G * 32) / 256, 256>>>(ph1, We1, be1);
    k_table<<<NB * (G / NCH), 256>>>(ph1);
    k_rows<<<G, 256>>>(ph1, e1, Wn1, bn1, Wm1, bm1, ALPHA, pmid);

    // ---- batchnorm ----
    k_bn<<<(G * 32) / 256, 256>>>(gam, bet);

    // ---- block 2 ----
    k_reset<<<RESET_GRID, 256>>>();
    k_edge<<<(NB * G * 32) / 256, 256>>>(pbn, We2, be2);
    k_table<<<NB * (G / NCH), 256>>>(pbn);
    k_rows<<<G, 256>>>(pbn, e2, Wn2, bn2, Wm2, bm2, BETA, out);

    (void)in_sizes; (void)n_in; (void)out_size;
}